// round 9
// baseline (speedup 1.0000x reference)
#include <cuda_runtime.h>
#include <cuda_bf16.h>

// Weighted BCE mean reduction, single fused kernel.
// loss_i = y_i==1 ? -log(x_i)*w1 : -log(1-x_i)*w0 ; out = mean(loss)
// N = 33554432. HBM-bound: 256 MB mandatory read at ~6.1 TB/s measured
// ceiling (stable across R1-R8; run noise ~±1us).
// R9: champion pattern with 512-thread blocks (592 = 148x4, one wave).
//     Same global interleave (stride 303104); halves block-reduce overhead.

#define RBLOCKS 592           // 148 SMs * 4 resident blocks (one full wave)
#define RTHREADS 512
#define LN2F 0.6931471805599453f

__device__ float g_partials[RBLOCKS];
__device__ unsigned int g_count;   // zero-init; reset by last block each replay

__global__ __launch_bounds__(RTHREADS, 4)
void wbce_kernel(const float4* __restrict__ x4,
                 const int4* __restrict__ y4,
                 const float* __restrict__ w,
                 int n4, float inv_n,
                 float* __restrict__ out)
{
    // fold -ln2 into the weights: -log(t)*w == log2(t) * (-w*ln2)
    const float lw0 = -__ldg(&w[0]) * LN2F;
    const float lw1 = -__ldg(&w[1]) * LN2F;

    float acc0 = 0.0f, acc1 = 0.0f;
    const int stride = gridDim.x * blockDim.x;
    int i = blockIdx.x * blockDim.x + threadIdx.x;

    for (; i + stride < n4; i += 2 * stride) {
        float4 xa = x4[i];
        int4   ya = y4[i];
        float4 xb = x4[i + stride];
        int4   yb = y4[i + stride];

        float t0 = (ya.x == 1) ? xa.x : (1.0f - xa.x);
        float t1 = (ya.y == 1) ? xa.y : (1.0f - xa.y);
        float t2 = (ya.z == 1) ? xa.z : (1.0f - xa.z);
        float t3 = (ya.w == 1) ? xa.w : (1.0f - xa.w);
        float t4 = (yb.x == 1) ? xb.x : (1.0f - xb.x);
        float t5 = (yb.y == 1) ? xb.y : (1.0f - xb.y);
        float t6 = (yb.z == 1) ? xb.z : (1.0f - xb.z);
        float t7 = (yb.w == 1) ? xb.w : (1.0f - xb.w);

        float u0 = (ya.x == 1) ? lw1 : lw0;
        float u1 = (ya.y == 1) ? lw1 : lw0;
        float u2 = (ya.z == 1) ? lw1 : lw0;
        float u3 = (ya.w == 1) ? lw1 : lw0;
        float u4 = (yb.x == 1) ? lw1 : lw0;
        float u5 = (yb.y == 1) ? lw1 : lw0;
        float u6 = (yb.z == 1) ? lw1 : lw0;
        float u7 = (yb.w == 1) ? lw1 : lw0;

        acc0 = fmaf(__log2f(t0), u0, acc0);
        acc1 = fmaf(__log2f(t1), u1, acc1);
        acc0 = fmaf(__log2f(t2), u2, acc0);
        acc1 = fmaf(__log2f(t3), u3, acc1);
        acc0 = fmaf(__log2f(t4), u4, acc0);
        acc1 = fmaf(__log2f(t5), u5, acc1);
        acc0 = fmaf(__log2f(t6), u6, acc0);
        acc1 = fmaf(__log2f(t7), u7, acc1);
    }
    // tail (at most one strided float4 per thread)
    for (; i < n4; i += stride) {
        float4 xv = x4[i];
        int4   yv = y4[i];
        float t0 = (yv.x == 1) ? xv.x : (1.0f - xv.x);
        float t1 = (yv.y == 1) ? xv.y : (1.0f - xv.y);
        float t2 = (yv.z == 1) ? xv.z : (1.0f - xv.z);
        float t3 = (yv.w == 1) ? xv.w : (1.0f - xv.w);
        float u0 = (yv.x == 1) ? lw1 : lw0;
        float u1 = (yv.y == 1) ? lw1 : lw0;
        float u2 = (yv.z == 1) ? lw1 : lw0;
        float u3 = (yv.w == 1) ? lw1 : lw0;
        acc0 = fmaf(__log2f(t0), u0, acc0);
        acc1 = fmaf(__log2f(t1), u1, acc1);
        acc0 = fmaf(__log2f(t2), u2, acc0);
        acc1 = fmaf(__log2f(t3), u3, acc1);
    }

    float acc = acc0 + acc1;

    // intra-block reduce
    #pragma unroll
    for (int off = 16; off > 0; off >>= 1)
        acc += __shfl_xor_sync(0xFFFFFFFFu, acc, off);

    __shared__ float warp_sums[RTHREADS / 32];
    __shared__ bool s_is_last;
    int lane = threadIdx.x & 31;
    int wid  = threadIdx.x >> 5;
    if (lane == 0) warp_sums[wid] = acc;
    __syncthreads();

    if (wid == 0) {
        float v = (lane < RTHREADS / 32) ? warp_sums[lane] : 0.0f;
        #pragma unroll
        for (int off = 16; off > 0; off >>= 1)
            v += __shfl_xor_sync(0xFFFFFFFFu, v, off);
        if (lane == 0) {
            g_partials[blockIdx.x] = v;
            __threadfence();
            unsigned int t = atomicAdd(&g_count, 1u);
            s_is_last = (t == gridDim.x - 1);
        }
    }
    __syncthreads();

    // last block folds all partials -> out
    if (s_is_last) {
        volatile float* parts = g_partials;
        float a = 0.0f;
        for (int j = threadIdx.x; j < RBLOCKS; j += RTHREADS)
            a += parts[j];

        #pragma unroll
        for (int off = 16; off > 0; off >>= 1)
            a += __shfl_xor_sync(0xFFFFFFFFu, a, off);

        if (lane == 0) warp_sums[wid] = a;
        __syncthreads();

        if (wid == 0) {
            float v = (lane < RTHREADS / 32) ? warp_sums[lane] : 0.0f;
            #pragma unroll
            for (int off = 16; off > 0; off >>= 1)
                v += __shfl_xor_sync(0xFFFFFFFFu, v, off);
            if (lane == 0) {
                out[0] = v * inv_n;
                g_count = 0;          // reset for next graph replay
            }
        }
    }
}

extern "C" void kernel_launch(void* const* d_in, const int* in_sizes, int n_in,
                              void* d_out, int out_size)
{
    const float* x = (const float*)d_in[0];
    const int*   y = (const int*)d_in[1];
    const float* w = (const float*)d_in[2];
    float* out = (float*)d_out;

    int n  = in_sizes[0];
    int n4 = n / 4;

    wbce_kernel<<<RBLOCKS, RTHREADS>>>(
        (const float4*)x, (const int4*)y, w, n4, 1.0f / (float)n, out);
}

// round 11
// speedup vs baseline: 1.0056x; 1.0056x over previous
#include <cuda_runtime.h>
#include <cuda_bf16.h>

// Weighted BCE mean reduction, single fused kernel. FINAL (champion config).
// loss_i = y_i==1 ? -log(x_i)*w1 : -log(1-x_i)*w0 ; out = mean(loss)
// N = 33554432. HBM-bound: 256 MB mandatory dual-stream read at ~6.1 TB/s
// measured ceiling (~76% of spec; stable across 9 rounds of variants:
// unroll 2/4, ldg/ldcs, interleaved/tiled, 128b/256b loads, 256/512 thr).
// Config: 1184x256 grid-stride (148 SMs x 8, one balanced wave), unroll-2
// with 4 front-batched LDG.128, log2-folded weights (1 MUFU + 1 FMA per
// element), fused last-block finalize (threadfence reduction).

#define RBLOCKS 1184          // 148 SMs * 8 resident blocks (one full wave)
#define RTHREADS 256
#define LN2F 0.6931471805599453f

__device__ float g_partials[RBLOCKS];
__device__ unsigned int g_count;   // zero-init; reset by last block each replay

__global__ __launch_bounds__(RTHREADS, 8)
void wbce_kernel(const float4* __restrict__ x4,
                 const int4* __restrict__ y4,
                 const float* __restrict__ w,
                 int n4, float inv_n,
                 float* __restrict__ out)
{
    // fold -ln2 into the weights: -log(t)*w == log2(t) * (-w*ln2)
    const float lw0 = -__ldg(&w[0]) * LN2F;
    const float lw1 = -__ldg(&w[1]) * LN2F;

    float acc0 = 0.0f, acc1 = 0.0f;
    const int stride = gridDim.x * blockDim.x;
    int i = blockIdx.x * blockDim.x + threadIdx.x;

    for (; i + stride < n4; i += 2 * stride) {
        float4 xa = x4[i];
        int4   ya = y4[i];
        float4 xb = x4[i + stride];
        int4   yb = y4[i + stride];

        float t0 = (ya.x == 1) ? xa.x : (1.0f - xa.x);
        float t1 = (ya.y == 1) ? xa.y : (1.0f - xa.y);
        float t2 = (ya.z == 1) ? xa.z : (1.0f - xa.z);
        float t3 = (ya.w == 1) ? xa.w : (1.0f - xa.w);
        float t4 = (yb.x == 1) ? xb.x : (1.0f - xb.x);
        float t5 = (yb.y == 1) ? xb.y : (1.0f - xb.y);
        float t6 = (yb.z == 1) ? xb.z : (1.0f - xb.z);
        float t7 = (yb.w == 1) ? xb.w : (1.0f - xb.w);

        float u0 = (ya.x == 1) ? lw1 : lw0;
        float u1 = (ya.y == 1) ? lw1 : lw0;
        float u2 = (ya.z == 1) ? lw1 : lw0;
        float u3 = (ya.w == 1) ? lw1 : lw0;
        float u4 = (yb.x == 1) ? lw1 : lw0;
        float u5 = (yb.y == 1) ? lw1 : lw0;
        float u6 = (yb.z == 1) ? lw1 : lw0;
        float u7 = (yb.w == 1) ? lw1 : lw0;

        acc0 = fmaf(__log2f(t0), u0, acc0);
        acc1 = fmaf(__log2f(t1), u1, acc1);
        acc0 = fmaf(__log2f(t2), u2, acc0);
        acc1 = fmaf(__log2f(t3), u3, acc1);
        acc0 = fmaf(__log2f(t4), u4, acc0);
        acc1 = fmaf(__log2f(t5), u5, acc1);
        acc0 = fmaf(__log2f(t6), u6, acc0);
        acc1 = fmaf(__log2f(t7), u7, acc1);
    }
    // tail (at most one strided float4 per thread)
    for (; i < n4; i += stride) {
        float4 xv = x4[i];
        int4   yv = y4[i];
        float t0 = (yv.x == 1) ? xv.x : (1.0f - xv.x);
        float t1 = (yv.y == 1) ? xv.y : (1.0f - xv.y);
        float t2 = (yv.z == 1) ? xv.z : (1.0f - xv.z);
        float t3 = (yv.w == 1) ? xv.w : (1.0f - xv.w);
        float u0 = (yv.x == 1) ? lw1 : lw0;
        float u1 = (yv.y == 1) ? lw1 : lw0;
        float u2 = (yv.z == 1) ? lw1 : lw0;
        float u3 = (yv.w == 1) ? lw1 : lw0;
        acc0 = fmaf(__log2f(t0), u0, acc0);
        acc1 = fmaf(__log2f(t1), u1, acc1);
        acc0 = fmaf(__log2f(t2), u2, acc0);
        acc1 = fmaf(__log2f(t3), u3, acc1);
    }

    float acc = acc0 + acc1;

    // intra-block reduce
    #pragma unroll
    for (int off = 16; off > 0; off >>= 1)
        acc += __shfl_xor_sync(0xFFFFFFFFu, acc, off);

    __shared__ float warp_sums[RTHREADS / 32];
    __shared__ bool s_is_last;
    int lane = threadIdx.x & 31;
    int wid  = threadIdx.x >> 5;
    if (lane == 0) warp_sums[wid] = acc;
    __syncthreads();

    if (wid == 0) {
        float v = (lane < RTHREADS / 32) ? warp_sums[lane] : 0.0f;
        #pragma unroll
        for (int off = 16; off > 0; off >>= 1)
            v += __shfl_xor_sync(0xFFFFFFFFu, v, off);
        if (lane == 0) {
            g_partials[blockIdx.x] = v;
            __threadfence();
            unsigned int t = atomicAdd(&g_count, 1u);
            s_is_last = (t == gridDim.x - 1);
        }
    }
    __syncthreads();

    // last block folds all partials -> out
    if (s_is_last) {
        volatile float* parts = g_partials;
        float a = 0.0f;
        for (int j = threadIdx.x; j < RBLOCKS; j += RTHREADS)
            a += parts[j];

        #pragma unroll
        for (int off = 16; off > 0; off >>= 1)
            a += __shfl_xor_sync(0xFFFFFFFFu, a, off);

        if (lane == 0) warp_sums[wid] = a;
        __syncthreads();

        if (wid == 0) {
            float v = (lane < RTHREADS / 32) ? warp_sums[lane] : 0.0f;
            #pragma unroll
            for (int off = 16; off > 0; off >>= 1)
                v += __shfl_xor_sync(0xFFFFFFFFu, v, off);
            if (lane == 0) {
                out[0] = v * inv_n;
                g_count = 0;          // reset for next graph replay
            }
        }
    }
}

extern "C" void kernel_launch(void* const* d_in, const int* in_sizes, int n_in,
                              void* d_out, int out_size)
{
    const float* x = (const float*)d_in[0];
    const int*   y = (const int*)d_in[1];
    const float* w = (const float*)d_in[2];
    float* out = (float*)d_out;

    int n  = in_sizes[0];
    int n4 = n / 4;

    wbce_kernel<<<RBLOCKS, RTHREADS>>>(
        (const float4*)x, (const int4*)y, w, n4, 1.0f / (float)n, out);
}